// round 1
// baseline (speedup 1.0000x reference)
#include <cuda_runtime.h>

// ---------------------------------------------------------------------------
// HVGGBlock: hyperbolic VGG block collapsed into tangent-space pipeline.
//   logmap0(project(expmap0(u)))  ==  clampnorm(u, R),  R = artanh(1-1e-4)
// Pipeline:
//   u0 = logmap0(x)
//   t1 = conv3x3(u0,w1,b1); v1 = clampnorm(t1)
//   BN1 stats over (N,H,W); v3 = relu(clampnorm(bn1(v1)))
//   t2 = conv3x3(v3,w2,b2); v4 = clampnorm(t2)
//   BN2; out = project(expmap0(relu(clampnorm(bn2(v4)))))
// ---------------------------------------------------------------------------

#define NB   8
#define CH   32
#define HH   256
#define WW   256
#define PLANE (HH*WW)            // 65536
#define IMG   (CH*PLANE)         // 2097152
#define NPIX  (NB*PLANE)         // 524288

#define R_CLAMP 4.9517188f       // artanh(0.9999)
#define MAXN    0.9999f

__device__ __align__(16) float g_bufA[NB*IMG];
__device__ __align__(16) float g_bufB[NB*IMG];
__device__ float g_stats[128];   // [0:32) sum1 [32:64) sq1 [64:96) sum2 [96:128) sq2
__device__ float g_aff[128];     // [0:32) scale1 [32:64) shift1 [64..) layer2

// ---- packed f32x2 helpers --------------------------------------------------
__device__ __forceinline__ unsigned long long pack2(float v) {
    unsigned long long r; unsigned u = __float_as_uint(v);
    asm("mov.b64 %0, {%1, %2};" : "=l"(r) : "r"(u), "r"(u));
    return r;
}
__device__ __forceinline__ void fma2(unsigned long long& d,
                                     unsigned long long a, unsigned long long b) {
    asm("fma.rn.f32x2 %0, %1, %2, %0;" : "+l"(d) : "l"(a), "l"(b));
}
__device__ __forceinline__ void unpack2(unsigned long long a, float& lo, float& hi) {
    unsigned x, y;
    asm("mov.b64 {%0, %1}, %2;" : "=r"(x), "=r"(y) : "l"(a));
    lo = __uint_as_float(x); hi = __uint_as_float(y);
}

// ---- k0: logmap0(x) -> bufA -------------------------------------------------
__global__ void __launch_bounds__(256) logmap_kernel(const float* __restrict__ x) {
    int p = blockIdx.x * 256 + threadIdx.x;       // 0 .. NPIX-1
    int n = p >> 16, hw = p & 65535;
    const float* xp = x + n * IMG + hw;
    float v[CH]; float ss = 0.f;
#pragma unroll
    for (int c = 0; c < CH; c++) { v[c] = xp[c << 16]; ss += v[c] * v[c]; }
    float nrm = sqrtf(ss);
    float nn  = fmaxf(nrm, 1e-5f);
    float t   = fminf(nn, 1.f - 1e-5f);
    float a   = 0.5f * (log1pf(t) - log1pf(-t));  // artanh (matches reference)
    float f   = a / nn;
    float* op = g_bufA + n * IMG + hw;
#pragma unroll
    for (int c = 0; c < CH; c++) op[c << 16] = v[c] * f;
}

// ---- conv3x3 (32->32) + clampnorm : bufA -> bufB ----------------------------
// Block 256 thr, output tile 32x32. Warp w -> rows 4w..4w+3, lane -> col.
// Each thread: 4 pixels x 32 couts, couts packed in f32x2 pairs.
#define TIN (CH*34*34)        // 36992 floats input tile
#define TWT (CH*9*CH)         // 9216 floats weights [cin][tap][cout]
#define SMEM_FLOATS (TIN + TWT + 32)

__global__ void __launch_bounds__(256, 1)
conv_kernel(const float* __restrict__ w, const float* __restrict__ bias) {
    extern __shared__ float smem[];
    float* s_in = smem;                    // [32][34][34]
    float* s_w  = smem + TIN;              // [cin][tap][cout]
    float* s_b  = smem + TIN + TWT;        // [32]

    const int tid = threadIdx.x;
    const int n   = blockIdx.z;
    const int gy0 = blockIdx.y * 32;
    const int gx0 = blockIdx.x * 32;

    // weights: s_w[(cin*9+t)*32 + cout] = w[cout][cin][t]
    for (int i = tid; i < TWT; i += 256) {
        int cout = i & 31;
        int rest = i >> 5;                 // cin*9 + t
        int t    = rest % 9;
        int cin  = rest / 9;
        s_w[i] = w[(cout * CH + cin) * 9 + t];
    }
    if (tid < CH) s_b[tid] = bias[tid];

    // input tile with zero padding
    const float* inN = g_bufA + n * IMG;
    for (int i = tid; i < TIN; i += 256) {
        int c   = i / 1156;
        int rem = i - c * 1156;
        int r   = rem / 34;
        int col = rem - r * 34;
        int gy = gy0 + r - 1, gx = gx0 + col - 1;
        float v = 0.f;
        if ((unsigned)gy < 256u && (unsigned)gx < 256u)
            v = inN[c * PLANE + gy * WW + gx];
        s_in[i] = v;
    }
    __syncthreads();

    const int warp = tid >> 5;
    const int lane = tid & 31;
    const int ry   = warp * 4;

    unsigned long long acc0[16], acc1[16], acc2[16], acc3[16];
#pragma unroll
    for (int cp = 0; cp < 16; cp++) {
        unsigned long long bp = *reinterpret_cast<const unsigned long long*>(&s_b[2 * cp]);
        acc0[cp] = bp; acc1[cp] = bp; acc2[cp] = bp; acc3[cp] = bp;
    }

    for (int cin = 0; cin < CH; ++cin) {
        const float* sp = s_in + cin * 1156 + ry * 34 + lane;
        float vin[6][3];
#pragma unroll
        for (int r = 0; r < 6; r++)
#pragma unroll
            for (int cc = 0; cc < 3; cc++)
                vin[r][cc] = sp[r * 34 + cc];

        const float* wp = s_w + cin * (9 * CH);
#pragma unroll
        for (int dy = 0; dy < 3; dy++) {
#pragma unroll
            for (int dx = 0; dx < 3; dx++) {
                const unsigned long long* w2 =
                    reinterpret_cast<const unsigned long long*>(wp + (dy * 3 + dx) * CH);
                unsigned long long p0 = pack2(vin[dy + 0][dx]);
                unsigned long long p1 = pack2(vin[dy + 1][dx]);
                unsigned long long p2 = pack2(vin[dy + 2][dx]);
                unsigned long long p3 = pack2(vin[dy + 3][dx]);
#pragma unroll
                for (int cp = 0; cp < 16; cp++) {
                    unsigned long long ww = w2[cp];
                    fma2(acc0[cp], p0, ww);
                    fma2(acc1[cp], p1, ww);
                    fma2(acc2[cp], p2, ww);
                    fma2(acc3[cp], p3, ww);
                }
            }
        }
    }

    float* outN = g_bufB + n * IMG;
#define EPILOG(ACC, I) {                                                         \
    float vals[32]; float ss = 0.f;                                              \
    _Pragma("unroll")                                                            \
    for (int cp = 0; cp < 16; cp++) {                                            \
        float lo, hi; unpack2(ACC[cp], lo, hi);                                  \
        vals[2*cp] = lo; vals[2*cp+1] = hi; ss += lo*lo + hi*hi;                 \
    }                                                                            \
    float nrm = sqrtf(ss);                                                       \
    float f = (nrm > R_CLAMP) ? (R_CLAMP / nrm) : 1.0f;                          \
    float* op = outN + (gy0 + ry + (I)) * WW + gx0 + lane;                       \
    _Pragma("unroll")                                                            \
    for (int c = 0; c < 32; c++) op[c * PLANE] = vals[c] * f; }

    EPILOG(acc0, 0)
    EPILOG(acc1, 1)
    EPILOG(acc2, 2)
    EPILOG(acc3, 3)
#undef EPILOG
}

// ---- stats over bufB: per-channel sum/sumsq ---------------------------------
__global__ void __launch_bounds__(256) stats_kernel(int statOff) {
    int c = blockIdx.y;
    int chunk = blockIdx.x;                 // 16 chunks of 32768 per channel
    int n = chunk >> 1;
    int off = (chunk & 1) * 32768;
    const float4* p = reinterpret_cast<const float4*>(g_bufB + n * IMG + c * PLANE + off);
    float s = 0.f, s2 = 0.f;
    for (int i = threadIdx.x; i < 8192; i += 256) {
        float4 v = p[i];
        s  += v.x + v.y + v.z + v.w;
        s2 += v.x*v.x + v.y*v.y + v.z*v.z + v.w*v.w;
    }
#pragma unroll
    for (int o = 16; o; o >>= 1) {
        s  += __shfl_xor_sync(0xffffffffu, s, o);
        s2 += __shfl_xor_sync(0xffffffffu, s2, o);
    }
    __shared__ float red[16];
    int warp = threadIdx.x >> 5, lane = threadIdx.x & 31;
    if (lane == 0) { red[warp] = s; red[8 + warp] = s2; }
    __syncthreads();
    if (threadIdx.x == 0) {
        float a = 0.f, b = 0.f;
#pragma unroll
        for (int ww = 0; ww < 8; ww++) { a += red[ww]; b += red[8 + ww]; }
        atomicAdd(&g_stats[statOff + c], a);
        atomicAdd(&g_stats[statOff + 32 + c], b);
    }
}

__global__ void zero_stats_kernel() {
    int t = threadIdx.x;
    if (t < 128) g_stats[t] = 0.f;
}

__global__ void finalize_kernel(int statOff, const float* __restrict__ g,
                                const float* __restrict__ beta, int affOff) {
    int c = threadIdx.x;
    if (c >= 32) return;
    const float inv = 1.0f / (float)NPIX;
    float m   = g_stats[statOff + c] * inv;
    float var = fmaxf(g_stats[statOff + 32 + c] * inv - m * m, 0.f);
    float is  = rsqrtf(var + 1e-5f);
    float sc  = g[c] * is;
    g_aff[affOff + c]      = sc;
    g_aff[affOff + 32 + c] = beta[c] - m * sc;
}

// ---- bn + clampnorm + relu : bufB -> bufA -----------------------------------
__global__ void __launch_bounds__(256) bnrelu_kernel(int affOff) {
    int p = blockIdx.x * 256 + threadIdx.x;
    int n = p >> 16, hw = p & 65535;
    const float* ip = g_bufB + n * IMG + hw;
    float u[CH]; float ss = 0.f;
#pragma unroll
    for (int c = 0; c < CH; c++) {
        float v = ip[c << 16];
        u[c] = v * g_aff[affOff + c] + g_aff[affOff + 32 + c];
        ss += u[c] * u[c];
    }
    float nrm = sqrtf(ss);
    float f = (nrm > R_CLAMP) ? (R_CLAMP / nrm) : 1.0f;
    float* op = g_bufA + n * IMG + hw;
#pragma unroll
    for (int c = 0; c < CH; c++) op[c << 16] = fmaxf(u[c] * f, 0.f);
}

// ---- bn + clampnorm + relu + expmap0 + project : bufB -> out ----------------
__global__ void __launch_bounds__(256) final_kernel(int affOff, float* __restrict__ out) {
    int p = blockIdx.x * 256 + threadIdx.x;
    int n = p >> 16, hw = p & 65535;
    const float* ip = g_bufB + n * IMG + hw;
    float u[CH]; float ss = 0.f;
#pragma unroll
    for (int c = 0; c < CH; c++) {
        float v = ip[c << 16];
        u[c] = v * g_aff[affOff + c] + g_aff[affOff + 32 + c];
        ss += u[c] * u[c];
    }
    float nrm = sqrtf(ss);
    float f1 = (nrm > R_CLAMP) ? (R_CLAMP / nrm) : 1.0f;
    float ss2 = 0.f;
#pragma unroll
    for (int c = 0; c < CH; c++) { u[c] = fmaxf(u[c] * f1, 0.f); ss2 += u[c] * u[c]; }
    float nrm2 = sqrtf(ss2);
    float nn  = fmaxf(nrm2, 1e-5f);
    float fac = tanhf(nn) / nn;              // expmap0
    float yn  = fac * nrm2;
    float pm  = fmaxf(yn, 1e-5f);
    float g2  = (pm > MAXN) ? (MAXN / pm) : 1.0f;   // project
    float wsc = fac * g2;
    float* op = out + n * IMG + hw;
#pragma unroll
    for (int c = 0; c < CH; c++) op[c << 16] = u[c] * wsc;
}

// ---------------------------------------------------------------------------
extern "C" void kernel_launch(void* const* d_in, const int* in_sizes, int n_in,
                              void* d_out, int out_size) {
    const float* x   = (const float*)d_in[0];
    const float* w1  = (const float*)d_in[1];
    const float* b1  = (const float*)d_in[2];
    const float* g1  = (const float*)d_in[3];
    const float* be1 = (const float*)d_in[4];
    const float* w2  = (const float*)d_in[5];
    const float* b2  = (const float*)d_in[6];
    const float* g2  = (const float*)d_in[7];
    const float* be2 = (const float*)d_in[8];
    float* out = (float*)d_out;

    const int SMEM = SMEM_FLOATS * (int)sizeof(float);   // ~185 KB
    cudaFuncSetAttribute(conv_kernel, cudaFuncAttributeMaxDynamicSharedMemorySize, SMEM);

    dim3 cgrid(WW / 32, HH / 32, NB);   // 8 x 8 x 8

    zero_stats_kernel<<<1, 128>>>();
    logmap_kernel<<<NPIX / 256, 256>>>(x);

    conv_kernel<<<cgrid, 256, SMEM>>>(w1, b1);
    stats_kernel<<<dim3(16, 32), 256>>>(0);
    finalize_kernel<<<1, 32>>>(0, g1, be1, 0);
    bnrelu_kernel<<<NPIX / 256, 256>>>(0);

    conv_kernel<<<cgrid, 256, SMEM>>>(w2, b2);
    stats_kernel<<<dim3(16, 32), 256>>>(64);
    finalize_kernel<<<1, 32>>>(64, g2, be2, 64);
    final_kernel<<<NPIX / 256, 256>>>(64, out);
}

// round 3
// speedup vs baseline: 1.6917x; 1.6917x over previous
#include <cuda_runtime.h>
#include <cstdint>

// ---------------------------------------------------------------------------
// HVGGBlock in tangent space; convs via mma.sync tf32 (HMMA) implicit GEMM.
//   logmap0(project(expmap0(u))) == clampnorm(u, R), R = artanh(1-1e-4)
// ---------------------------------------------------------------------------

#define NB   8
#define CH   32
#define HH   256
#define WW   256
#define PLANE (HH*WW)
#define IMG   (CH*PLANE)
#define NPIX  (NB*PLANE)

#define R_CLAMP 4.9517188f
#define MAXN    0.9999f

__device__ __align__(16) float g_bufA[NB*IMG];
__device__ __align__(16) float g_bufB[NB*IMG];
__device__ float g_stats[128];
__device__ float g_aff[128];

__device__ __forceinline__ uint32_t f2tf32(float f) {
    uint32_t r; asm("cvt.rna.tf32.f32 %0, %1;" : "=r"(r) : "f"(f)); return r;
}

// ---- conv smem layout --------------------------------------------------------
// s_in : 32 ch x 1160 u32 (34x34 halo tile, row stride 34, ch stride padded 1160)
// s_w  : 36 ksteps x 4 Ntiles x 32 lanes x {b0,b1} u32  (per-fragment packed)
// s_b  : 32 f32 bias
#define CIN_STRIDE 1160
#define SIN_U32   (CH*CIN_STRIDE)          // 37120
#define SW_OFF    SIN_U32                  // u32 index
#define SW_U32    (36*4*32*2)              // 9216
#define SB_OFF    (SW_OFF + SW_U32)        // 46336
#define SMEM_U32  (SB_OFF + 32)            // 46368
#define SMEM_BYTES (SMEM_U32*4)            // 185472

__global__ void __launch_bounds__(256, 1)
conv_mma_kernel(const float* __restrict__ w, const float* __restrict__ bias) {
    extern __shared__ __align__(16) uint32_t smem[];
    uint32_t* s_in = smem;
    uint32_t* s_w  = smem + SW_OFF;
    float*    s_b  = (float*)(smem + SB_OFF);

    const int tid  = threadIdx.x;
    const int wid  = tid >> 5;
    const int lane = tid & 31;
    const int gid  = lane >> 2;          // groupID
    const int tig  = lane & 3;           // threadID_in_group
    const int n    = blockIdx.z;
    const int gy0  = blockIdx.y * 32;
    const int gx0  = blockIdx.x * 32;

    if (tid < 32) s_b[tid] = bias[tid];

    // ---- weights: per-fragment pack, K ordering k = tap*32 + cin -------------
    // entry id -> (s, Nt, lane): b0 = W[co][k=s*8+tig], b1 = W[co][k=s*8+tig+4]
    for (int id = tid; id < 36 * 4 * 32; id += 256) {
        int l  = id & 31;
        int Nt = (id >> 5) & 3;
        int s  = id >> 7;
        int tg = l & 3, gd = l >> 2;
        int co = Nt * 8 + gd;
        int t  = s >> 2;
        int c0 = (s & 3) * 8 + tg;
        int c1 = c0 + 4;
        uint32_t b0 = f2tf32(w[(co * CH + c0) * 9 + t]);
        uint32_t b1 = f2tf32(w[(co * CH + c1) * 9 + t]);
        s_w[id * 2]     = b0;
        s_w[id * 2 + 1] = b1;
    }

    // ---- input halo tile, tf32 bits, padded channel stride -------------------
    const float* inN = g_bufA + n * IMG;
    for (int id = tid; id < CH * 1156; id += 256) {
        int ci  = id / 1156;
        int rem = id - ci * 1156;
        int r   = rem / 34;
        int c   = rem - r * 34;
        int gy = gy0 + r - 1, gx = gx0 + c - 1;
        float v = 0.f;
        if ((unsigned)gy < 256u && (unsigned)gx < 256u)
            v = inN[ci * PLANE + gy * WW + gx];
        s_in[ci * CIN_STRIDE + r * 34 + c] = f2tf32(v);
    }
    __syncthreads();

    // ---- implicit GEMM: M=1024 px, N=32, K=288 -------------------------------
    // warp wid owns pixel rows 4*wid .. 4*wid+3 (8 M-tiles of 16 px)
    float acc[8][4][4];
#pragma unroll
    for (int i = 0; i < 8; i++)
#pragma unroll
        for (int Nt = 0; Nt < 4; Nt++)
#pragma unroll
            for (int j = 0; j < 4; j++) acc[i][Nt][j] = 0.f;

    const int warp_row = wid * 4;

#pragma unroll 2
    for (int s = 0; s < 36; s++) {
        int t  = s >> 2;
        int ky = (t >= 6) ? 2 : (t >= 3 ? 1 : 0);
        int kx = t - ky * 3;
        int ci0 = (s & 3) * 8 + tig;

        uint32_t b[4][2];
#pragma unroll
        for (int Nt = 0; Nt < 4; Nt++) {
            uint2 bb = *(const uint2*)(s_w + ((s * 4 + Nt) * 32 + lane) * 2);
            b[Nt][0] = bb.x; b[Nt][1] = bb.y;
        }

        int base = ci0 * CIN_STRIDE + (warp_row + ky) * 34 + kx + gid;
#pragma unroll
        for (int i = 0; i < 8; i++) {
            int addr = base + (i >> 1) * 34 + (i & 1) * 16;
            uint32_t a0 = s_in[addr];
            uint32_t a1 = s_in[addr + 8];
            uint32_t a2 = s_in[addr + 4 * CIN_STRIDE];
            uint32_t a3 = s_in[addr + 4 * CIN_STRIDE + 8];
#pragma unroll
            for (int Nt = 0; Nt < 4; Nt++) {
                asm volatile(
                    "mma.sync.aligned.m16n8k8.row.col.f32.tf32.tf32.f32 "
                    "{%0,%1,%2,%3}, {%4,%5,%6,%7}, {%8,%9}, {%0,%1,%2,%3};"
                    : "+f"(acc[i][Nt][0]), "+f"(acc[i][Nt][1]),
                      "+f"(acc[i][Nt][2]), "+f"(acc[i][Nt][3])
                    : "r"(a0), "r"(a1), "r"(a2), "r"(a3),
                      "r"(b[Nt][0]), "r"(b[Nt][1]));
            }
        }
    }

    // ---- epilogue: bias + per-pixel clampnorm (quad reduction) ---------------
    float2 bs[4];
#pragma unroll
    for (int Nt = 0; Nt < 4; Nt++)
        bs[Nt] = *(const float2*)(s_b + Nt * 8 + 2 * tig);

    float* outN = g_bufB + n * IMG;
#pragma unroll
    for (int i = 0; i < 8; i++) {
        int yl = warp_row + (i >> 1);
        int xl = (i & 1) * 16 + gid;
        float vA[8], vB[8];
        float ssA = 0.f, ssB = 0.f;
#pragma unroll
        for (int Nt = 0; Nt < 4; Nt++) {
            float a0 = acc[i][Nt][0] + bs[Nt].x;
            float a1 = acc[i][Nt][1] + bs[Nt].y;
            float b0 = acc[i][Nt][2] + bs[Nt].x;
            float b1 = acc[i][Nt][3] + bs[Nt].y;
            vA[2 * Nt] = a0; vA[2 * Nt + 1] = a1;
            vB[2 * Nt] = b0; vB[2 * Nt + 1] = b1;
            ssA += a0 * a0 + a1 * a1;
            ssB += b0 * b0 + b1 * b1;
        }
        ssA += __shfl_xor_sync(0xffffffffu, ssA, 1);
        ssA += __shfl_xor_sync(0xffffffffu, ssA, 2);
        ssB += __shfl_xor_sync(0xffffffffu, ssB, 1);
        ssB += __shfl_xor_sync(0xffffffffu, ssB, 2);
        float nA = sqrtf(ssA), nB = sqrtf(ssB);
        float fA = (nA > R_CLAMP) ? (R_CLAMP / nA) : 1.0f;
        float fB = (nB > R_CLAMP) ? (R_CLAMP / nB) : 1.0f;
        float* opA = outN + (gy0 + yl) * WW + gx0 + xl;
        float* opB = opA + 8;
#pragma unroll
        for (int Nt = 0; Nt < 4; Nt++) {
            int co = Nt * 8 + 2 * tig;
            opA[co * PLANE]       = vA[2 * Nt] * fA;
            opA[(co + 1) * PLANE] = vA[2 * Nt + 1] * fA;
            opB[co * PLANE]       = vB[2 * Nt] * fB;
            opB[(co + 1) * PLANE] = vB[2 * Nt + 1] * fB;
        }
    }
}

// ---- logmap0(x) -> bufA ------------------------------------------------------
__global__ void __launch_bounds__(256) logmap_kernel(const float* __restrict__ x) {
    int p = blockIdx.x * 256 + threadIdx.x;
    int n = p >> 16, hw = p & 65535;
    const float* xp = x + n * IMG + hw;
    float v[CH]; float ss = 0.f;
#pragma unroll
    for (int c = 0; c < CH; c++) { v[c] = xp[c << 16]; ss += v[c] * v[c]; }
    float nrm = sqrtf(ss);
    float nn  = fmaxf(nrm, 1e-5f);
    float t   = fminf(nn, 1.f - 1e-5f);
    float a   = 0.5f * (log1pf(t) - log1pf(-t));
    float f   = a / nn;
    float* op = g_bufA + n * IMG + hw;
#pragma unroll
    for (int c = 0; c < CH; c++) op[c << 16] = v[c] * f;
}

// ---- per-channel sum/sumsq over bufB ----------------------------------------
__global__ void __launch_bounds__(256) stats_kernel(int statOff) {
    int c = blockIdx.y;
    int chunk = blockIdx.x;
    int n = chunk >> 1;
    int off = (chunk & 1) * 32768;
    const float4* p = reinterpret_cast<const float4*>(g_bufB + n * IMG + c * PLANE + off);
    float s = 0.f, s2 = 0.f;
    for (int i = threadIdx.x; i < 8192; i += 256) {
        float4 v = p[i];
        s  += v.x + v.y + v.z + v.w;
        s2 += v.x*v.x + v.y*v.y + v.z*v.z + v.w*v.w;
    }
#pragma unroll
    for (int o = 16; o; o >>= 1) {
        s  += __shfl_xor_sync(0xffffffffu, s, o);
        s2 += __shfl_xor_sync(0xffffffffu, s2, o);
    }
    __shared__ float red[16];
    int warp = threadIdx.x >> 5, lane = threadIdx.x & 31;
    if (lane == 0) { red[warp] = s; red[8 + warp] = s2; }
    __syncthreads();
    if (threadIdx.x == 0) {
        float a = 0.f, b = 0.f;
#pragma unroll
        for (int ww = 0; ww < 8; ww++) { a += red[ww]; b += red[8 + ww]; }
        atomicAdd(&g_stats[statOff + c], a);
        atomicAdd(&g_stats[statOff + 32 + c], b);
    }
}

__global__ void zero_stats_kernel() {
    int t = threadIdx.x;
    if (t < 128) g_stats[t] = 0.f;
}

__global__ void finalize_kernel(int statOff, const float* __restrict__ g,
                                const float* __restrict__ beta, int affOff) {
    int c = threadIdx.x;
    if (c >= 32) return;
    const float inv = 1.0f / (float)NPIX;
    float m   = g_stats[statOff + c] * inv;
    float var = fmaxf(g_stats[statOff + 32 + c] * inv - m * m, 0.f);
    float is  = rsqrtf(var + 1e-5f);
    float sc  = g[c] * is;
    g_aff[affOff + c]      = sc;
    g_aff[affOff + 32 + c] = beta[c] - m * sc;
}

// ---- bn + clampnorm + relu : bufB -> bufA -----------------------------------
__global__ void __launch_bounds__(256) bnrelu_kernel(int affOff) {
    int p = blockIdx.x * 256 + threadIdx.x;
    int n = p >> 16, hw = p & 65535;
    const float* ip = g_bufB + n * IMG + hw;
    float u[CH]; float ss = 0.f;
#pragma unroll
    for (int c = 0; c < CH; c++) {
        float v = ip[c << 16];
        u[c] = v * g_aff[affOff + c] + g_aff[affOff + 32 + c];
        ss += u[c] * u[c];
    }
    float nrm = sqrtf(ss);
    float f = (nrm > R_CLAMP) ? (R_CLAMP / nrm) : 1.0f;
    float* op = g_bufA + n * IMG + hw;
#pragma unroll
    for (int c = 0; c < CH; c++) op[c << 16] = fmaxf(u[c] * f, 0.f);
}

// ---- bn + clampnorm + relu + expmap0 + project : bufB -> out ----------------
__global__ void __launch_bounds__(256) final_kernel(int affOff, float* __restrict__ out) {
    int p = blockIdx.x * 256 + threadIdx.x;
    int n = p >> 16, hw = p & 65535;
    const float* ip = g_bufB + n * IMG + hw;
    float u[CH]; float ss = 0.f;
#pragma unroll
    for (int c = 0; c < CH; c++) {
        float v = ip[c << 16];
        u[c] = v * g_aff[affOff + c] + g_aff[affOff + 32 + c];
        ss += u[c] * u[c];
    }
    float nrm = sqrtf(ss);
    float f1 = (nrm > R_CLAMP) ? (R_CLAMP / nrm) : 1.0f;
    float ss2 = 0.f;
#pragma unroll
    for (int c = 0; c < CH; c++) { u[c] = fmaxf(u[c] * f1, 0.f); ss2 += u[c] * u[c]; }
    float nrm2 = sqrtf(ss2);
    float nn  = fmaxf(nrm2, 1e-5f);
    float fac = tanhf(nn) / nn;
    float yn  = fac * nrm2;
    float pm  = fmaxf(yn, 1e-5f);
    float g2  = (pm > MAXN) ? (MAXN / pm) : 1.0f;
    float wsc = fac * g2;
    float* op = out + n * IMG + hw;
#pragma unroll
    for (int c = 0; c < CH; c++) op[c << 16] = u[c] * wsc;
}

// ---------------------------------------------------------------------------
extern "C" void kernel_launch(void* const* d_in, const int* in_sizes, int n_in,
                              void* d_out, int out_size) {
    const float* x   = (const float*)d_in[0];
    const float* w1  = (const float*)d_in[1];
    const float* b1  = (const float*)d_in[2];
    const float* g1  = (const float*)d_in[3];
    const float* be1 = (const float*)d_in[4];
    const float* w2  = (const float*)d_in[5];
    const float* b2  = (const float*)d_in[6];
    const float* g2  = (const float*)d_in[7];
    const float* be2 = (const float*)d_in[8];
    float* out = (float*)d_out;

    cudaFuncSetAttribute(conv_mma_kernel,
                         cudaFuncAttributeMaxDynamicSharedMemorySize, SMEM_BYTES);

    dim3 cgrid(WW / 32, HH / 32, NB);   // 8 x 8 x 8

    zero_stats_kernel<<<1, 128>>>();
    logmap_kernel<<<NPIX / 256, 256>>>(x);

    conv_mma_kernel<<<cgrid, 256, SMEM_BYTES>>>(w1, b1);
    stats_kernel<<<dim3(16, 32), 256>>>(0);
    finalize_kernel<<<1, 32>>>(0, g1, be1, 0);
    bnrelu_kernel<<<NPIX / 256, 256>>>(0);

    conv_mma_kernel<<<cgrid, 256, SMEM_BYTES>>>(w2, b2);
    stats_kernel<<<dim3(16, 32), 256>>>(64);
    finalize_kernel<<<1, 32>>>(64, g2, be2, 64);
    final_kernel<<<NPIX / 256, 256>>>(64, out);
}

// round 5
// speedup vs baseline: 3.6606x; 2.1639x over previous
#include <cuda_runtime.h>
#include <cstdint>

// ---------------------------------------------------------------------------
// HVGGBlock in tangent space; convs via mma.sync tf32 implicit GEMM, with
// logmap fused into conv1's tile build and BN+clamp+relu fused into conv2's.
//   logmap0(project(expmap0(u))) == clampnorm(u, R), R = artanh(1-1e-4)
// ---------------------------------------------------------------------------

#define NB   8
#define CH   32
#define HH   256
#define WW   256
#define PLANE (HH*WW)
#define IMG   (CH*PLANE)
#define NPIX  (NB*PLANE)

#define R_CLAMP 4.9517188f
#define MAXN    0.9999f

__device__ __align__(16) float g_bufA[NB*IMG];
__device__ __align__(16) float g_bufB[NB*IMG];
__device__ float g_stats[128];
__device__ float g_aff[128];
__device__ __align__(16) uint32_t g_wpack[2*36*4*32*2];   // per-fragment packed

__device__ __forceinline__ uint32_t f2tf32(float f) {
    uint32_t r; asm("cvt.rna.tf32.f32 %0, %1;" : "=r"(r) : "f"(f)); return r;
}

// ---- weight pack: [layer][s][Nt][lane] -> {b0,b1} ---------------------------
// 4608 entries per layer (36 ksteps x 4 Ntiles x 32 lanes), 9216 total.
__global__ void __launch_bounds__(256) pack_w_kernel(const float* __restrict__ w1,
                                                     const float* __restrict__ w2) {
    int id = blockIdx.x * 256 + threadIdx.x;
    if (id >= 9216) return;
    int lay = id / 4608;             // FIX (was id >> 12): layer stride is 4608
    int r   = id - lay * 4608;
    int l   = r & 31;
    int Nt  = (r >> 5) & 3;
    int s   = r >> 7;                // 0..35
    int tg = l & 3, gd = l >> 2;
    int co = Nt * 8 + gd;
    int t  = s >> 2;
    int c0 = (s & 3) * 8 + tg;
    const float* w = lay ? w2 : w1;
    uint32_t b0 = f2tf32(w[(co * CH + c0) * 9 + t]);
    uint32_t b1 = f2tf32(w[(co * CH + c0 + 4) * 9 + t]);
    uint2* dst = (uint2*)(g_wpack + lay * 9216);
    dst[(s * 4 + Nt) * 32 + l] = make_uint2(b0, b1);
}

// ---- fused conv kernel -------------------------------------------------------
// Tile: 32 wide x 16 tall output, halo 34x18 = 612 pixels.
// smem: 16 channel-pairs x 620 pixels x uint2 (tf32 bits of ch q, q+4-of-group)
#define PSTRIDE 620
#define SMEM_BYTES (16*PSTRIDE*8)     // 79360

// MODE 0: src = x (external), logmap transform, dst = g_bufB, layer 0
// MODE 1: src = g_bufB, BN-affine+clampnorm+relu (aff @ 0), dst = g_bufA, layer 1
template<int MODE>
__global__ void __launch_bounds__(256, 2)
conv_fused_kernel(const float* __restrict__ ext, const float* __restrict__ bias) {
    extern __shared__ __align__(16) uint2 s_in[];   // [16][PSTRIDE]

    const int tid  = threadIdx.x;
    const int wid  = tid >> 5;
    const int lane = tid & 31;
    const int gid  = lane >> 2;
    const int tig  = lane & 3;
    const int n    = blockIdx.z;
    const int gy0  = blockIdx.y * 16;
    const int gx0  = blockIdx.x * 32;

    const float* src = (MODE == 0) ? (ext + n * IMG) : (g_bufB + n * IMG);

    // ---- build: per-pixel transform + pair-layout tf32 store ----------------
    for (int p = tid; p < 612; p += 256) {
        int r = p / 34, c = p - r * 34;
        int gy = gy0 + r - 1, gx = gx0 + c - 1;
        bool inb = ((unsigned)gy < 256u) && ((unsigned)gx < 256u);
        float v[CH];
        if (inb) {
            const float* sp = src + gy * WW + gx;
            float ss = 0.f;
#pragma unroll
            for (int ci = 0; ci < CH; ci++) {
                float u = sp[ci * PLANE];
                if (MODE == 1) u = u * g_aff[ci] + g_aff[32 + ci];
                v[ci] = u; ss += u * u;
            }
            float f;
            if (MODE == 0) {
                float nrm = sqrtf(ss);
                float nn  = fmaxf(nrm, 1e-5f);
                float t   = fminf(nn, 1.f - 1e-5f);
                f = 0.5f * (log1pf(t) - log1pf(-t)) / nn;          // logmap0
            } else {
                float nrm = sqrtf(ss);
                f = (nrm > R_CLAMP) ? (R_CLAMP / nrm) : 1.0f;      // clampnorm
            }
#pragma unroll
            for (int ci = 0; ci < CH; ci++) {
                float u = v[ci] * f;
                if (MODE == 1) u = fmaxf(u, 0.f);                  // relu
                v[ci] = u;
            }
        } else {
#pragma unroll
            for (int ci = 0; ci < CH; ci++) v[ci] = 0.f;
        }
#pragma unroll
        for (int g = 0; g < 4; g++)
#pragma unroll
            for (int q4 = 0; q4 < 4; q4++)
                s_in[(g * 4 + q4) * PSTRIDE + p] =
                    make_uint2(f2tf32(v[g * 8 + q4]), f2tf32(v[g * 8 + q4 + 4]));
    }
    __syncthreads();

    // ---- implicit GEMM: warp owns 2 pixel rows, 4 M-tiles, N=32 -------------
    const uint2* wp = (const uint2*)(g_wpack + MODE * 9216);
    float acc[4][4][4];
#pragma unroll
    for (int i = 0; i < 4; i++)
#pragma unroll
        for (int Nt = 0; Nt < 4; Nt++)
#pragma unroll
            for (int j = 0; j < 4; j++) acc[i][Nt][j] = 0.f;

    const int warp_row = wid * 2;

#pragma unroll 4
    for (int s = 0; s < 36; s++) {
        int t  = s >> 2;
        int ky = (t >= 6) ? 2 : (t >= 3 ? 1 : 0);
        int kx = t - ky * 3;
        int q  = (s & 3) * 4 + tig;

        uint2 b[4];
#pragma unroll
        for (int Nt = 0; Nt < 4; Nt++) b[Nt] = wp[(s * 4 + Nt) * 32 + lane];

        int pixbase = q * PSTRIDE + (warp_row + ky) * 34 + kx + gid;
#pragma unroll
        for (int i = 0; i < 4; i++) {
            int px = pixbase + (i >> 1) * 34 + (i & 1) * 16;
            uint2 A0 = s_in[px];          // (a0 = ch q, a2 = ch q+4) @ row gid
            uint2 A1 = s_in[px + 8];      // (a1, a3)                @ row gid+8
#pragma unroll
            for (int Nt = 0; Nt < 4; Nt++) {
                asm volatile(
                    "mma.sync.aligned.m16n8k8.row.col.f32.tf32.tf32.f32 "
                    "{%0,%1,%2,%3}, {%4,%5,%6,%7}, {%8,%9}, {%0,%1,%2,%3};"
                    : "+f"(acc[i][Nt][0]), "+f"(acc[i][Nt][1]),
                      "+f"(acc[i][Nt][2]), "+f"(acc[i][Nt][3])
                    : "r"(A0.x), "r"(A1.x), "r"(A0.y), "r"(A1.y),
                      "r"(b[Nt].x), "r"(b[Nt].y));
            }
        }
    }

    // ---- epilogue: bias + per-pixel clampnorm + store ------------------------
    float2 bs[4];
#pragma unroll
    for (int Nt = 0; Nt < 4; Nt++)
        bs[Nt] = *(const float2*)(bias + Nt * 8 + 2 * tig);

    float* outN = (MODE == 0 ? g_bufB : g_bufA) + n * IMG;
#pragma unroll
    for (int i = 0; i < 4; i++) {
        int yl = warp_row + (i >> 1);
        int xl = (i & 1) * 16 + gid;
        float vA[8], vB[8];
        float ssA = 0.f, ssB = 0.f;
#pragma unroll
        for (int Nt = 0; Nt < 4; Nt++) {
            float a0 = acc[i][Nt][0] + bs[Nt].x;
            float a1 = acc[i][Nt][1] + bs[Nt].y;
            float b0 = acc[i][Nt][2] + bs[Nt].x;
            float b1 = acc[i][Nt][3] + bs[Nt].y;
            vA[2 * Nt] = a0; vA[2 * Nt + 1] = a1;
            vB[2 * Nt] = b0; vB[2 * Nt + 1] = b1;
            ssA += a0 * a0 + a1 * a1;
            ssB += b0 * b0 + b1 * b1;
        }
        ssA += __shfl_xor_sync(0xffffffffu, ssA, 1);
        ssA += __shfl_xor_sync(0xffffffffu, ssA, 2);
        ssB += __shfl_xor_sync(0xffffffffu, ssB, 1);
        ssB += __shfl_xor_sync(0xffffffffu, ssB, 2);
        float nA = sqrtf(ssA), nB = sqrtf(ssB);
        float fA = (nA > R_CLAMP) ? (R_CLAMP / nA) : 1.0f;
        float fB = (nB > R_CLAMP) ? (R_CLAMP / nB) : 1.0f;
        float* opA = outN + (gy0 + yl) * WW + gx0 + xl;
        float* opB = opA + 8;
#pragma unroll
        for (int Nt = 0; Nt < 4; Nt++) {
            int co = Nt * 8 + 2 * tig;
            opA[co * PLANE]       = vA[2 * Nt] * fA;
            opA[(co + 1) * PLANE] = vA[2 * Nt + 1] * fA;
            opB[co * PLANE]       = vB[2 * Nt] * fB;
            opB[(co + 1) * PLANE] = vB[2 * Nt + 1] * fB;
        }
    }
}

// ---- per-channel sum/sumsq (which: 0 = bufB, 1 = bufA) -----------------------
__global__ void __launch_bounds__(256) stats_kernel(int statOff, int which) {
    const float* buf = which ? g_bufA : g_bufB;
    int c = blockIdx.y;
    int chunk = blockIdx.x;
    int n = chunk >> 1;
    int off = (chunk & 1) * 32768;
    const float4* p = reinterpret_cast<const float4*>(buf + n * IMG + c * PLANE + off);
    float s = 0.f, s2 = 0.f;
    for (int i = threadIdx.x; i < 8192; i += 256) {
        float4 v = p[i];
        s  += v.x + v.y + v.z + v.w;
        s2 += v.x*v.x + v.y*v.y + v.z*v.z + v.w*v.w;
    }
#pragma unroll
    for (int o = 16; o; o >>= 1) {
        s  += __shfl_xor_sync(0xffffffffu, s, o);
        s2 += __shfl_xor_sync(0xffffffffu, s2, o);
    }
    __shared__ float red[16];
    int warp = threadIdx.x >> 5, lane = threadIdx.x & 31;
    if (lane == 0) { red[warp] = s; red[8 + warp] = s2; }
    __syncthreads();
    if (threadIdx.x == 0) {
        float a = 0.f, b = 0.f;
#pragma unroll
        for (int ww = 0; ww < 8; ww++) { a += red[ww]; b += red[8 + ww]; }
        atomicAdd(&g_stats[statOff + c], a);
        atomicAdd(&g_stats[statOff + 32 + c], b);
    }
}

__global__ void zero_stats_kernel() {
    int t = threadIdx.x;
    if (t < 128) g_stats[t] = 0.f;
}

__global__ void finalize_kernel(int statOff, const float* __restrict__ g,
                                const float* __restrict__ beta, int affOff) {
    int c = threadIdx.x;
    if (c >= 32) return;
    const float inv = 1.0f / (float)NPIX;
    float m   = g_stats[statOff + c] * inv;
    float var = fmaxf(g_stats[statOff + 32 + c] * inv - m * m, 0.f);
    float is  = rsqrtf(var + 1e-5f);
    float sc  = g[c] * is;
    g_aff[affOff + c]      = sc;
    g_aff[affOff + 32 + c] = beta[c] - m * sc;
}

// ---- bn + clampnorm + relu + expmap0 + project : bufA -> out -----------------
__global__ void __launch_bounds__(256) final_kernel(int affOff, float* __restrict__ out) {
    int p = blockIdx.x * 256 + threadIdx.x;
    int n = p >> 16, hw = p & 65535;
    const float* ip = g_bufA + n * IMG + hw;
    float u[CH]; float ss = 0.f;
#pragma unroll
    for (int c = 0; c < CH; c++) {
        float v = ip[c << 16];
        u[c] = v * g_aff[affOff + c] + g_aff[affOff + 32 + c];
        ss += u[c] * u[c];
    }
    float nrm = sqrtf(ss);
    float f1 = (nrm > R_CLAMP) ? (R_CLAMP / nrm) : 1.0f;
    float ss2 = 0.f;
#pragma unroll
    for (int c = 0; c < CH; c++) { u[c] = fmaxf(u[c] * f1, 0.f); ss2 += u[c] * u[c]; }
    float nrm2 = sqrtf(ss2);
    float nn  = fmaxf(nrm2, 1e-5f);
    float fac = tanhf(nn) / nn;
    float yn  = fac * nrm2;
    float pm  = fmaxf(yn, 1e-5f);
    float g2  = (pm > MAXN) ? (MAXN / pm) : 1.0f;
    float wsc = fac * g2;
    float* op = out + n * IMG + hw;
#pragma unroll
    for (int c = 0; c < CH; c++) op[c << 16] = u[c] * wsc;
}

// ---------------------------------------------------------------------------
extern "C" void kernel_launch(void* const* d_in, const int* in_sizes, int n_in,
                              void* d_out, int out_size) {
    const float* x   = (const float*)d_in[0];
    const float* w1  = (const float*)d_in[1];
    const float* b1  = (const float*)d_in[2];
    const float* g1  = (const float*)d_in[3];
    const float* be1 = (const float*)d_in[4];
    const float* w2  = (const float*)d_in[5];
    const float* b2  = (const float*)d_in[6];
    const float* g2  = (const float*)d_in[7];
    const float* be2 = (const float*)d_in[8];
    float* out = (float*)d_out;

    cudaFuncSetAttribute(conv_fused_kernel<0>,
                         cudaFuncAttributeMaxDynamicSharedMemorySize, SMEM_BYTES);
    cudaFuncSetAttribute(conv_fused_kernel<1>,
                         cudaFuncAttributeMaxDynamicSharedMemorySize, SMEM_BYTES);

    dim3 cgrid(WW / 32, HH / 16, NB);   // 8 x 16 x 8 = 1024 CTAs

    zero_stats_kernel<<<1, 128>>>();
    pack_w_kernel<<<36, 256>>>(w1, w2);

    conv_fused_kernel<0><<<cgrid, 256, SMEM_BYTES>>>(x, b1);      // x -> bufB
    stats_kernel<<<dim3(16, 32), 256>>>(0, 0);
    finalize_kernel<<<1, 32>>>(0, g1, be1, 0);

    conv_fused_kernel<1><<<cgrid, 256, SMEM_BYTES>>>(nullptr, b2); // bufB -> bufA
    stats_kernel<<<dim3(16, 32), 256>>>(64, 1);
    finalize_kernel<<<1, 32>>>(64, g2, be2, 64);
    final_kernel<<<NPIX / 256, 256>>>(64, out);
}